// round 3
// baseline (speedup 1.0000x reference)
#include <cuda_runtime.h>
#include <cstdint>
#include <cstddef>

// ---------------------------------------------------------------------------
// Problem constants
// ---------------------------------------------------------------------------
#define BSZ       8
#define SEQ       1024
#define DIM       1024
#define NHEAD     16
#define HDIM      64
#define MTOT      (BSZ * SEQ)        // 8192
#define CATD      (DIM + HDIM)       // 1088
#define FFD       (2 * DIM)          // 2048

// ---------------------------------------------------------------------------
// Scratch (static device globals; no allocation in kernel_launch)
// ---------------------------------------------------------------------------
__device__ float g_Q[(size_t)BSZ * NHEAD * SEQ * HDIM];   // [b,h,n,d] (pre-scaled)
__device__ float g_K[(size_t)BSZ * NHEAD * SEQ * HDIM];
__device__ float g_V[(size_t)BSZ * NHEAD * SEQ * HDIM];
__device__ float g_CAT[(size_t)MTOT * CATD];              // [row, 1088]: attn out | in_
__device__ float g_H1[(size_t)MTOT * FFD];                // relu(cat @ W1 + b1)

// ---------------------------------------------------------------------------
// Generic tiled SGEMM: C = op(A[M,K] @ B[K,N] + bias) with fused epilogue.
//   attn_mode=1 -> scatter into [b,h,n,d] layout (for Q/K/V)
//   else        -> C[row*ldc + col_off + col]
// 128x128 tile, BK=16, 256 threads, 8x8 per-thread micro tile.
// ---------------------------------------------------------------------------
#define BM 128
#define BN 128
#define BK 16

__global__ __launch_bounds__(256) void sgemm_kernel(
    const float* __restrict__ A, const float* __restrict__ B,
    const float* __restrict__ bias, float* __restrict__ C,
    int M, int N, int K, int ldc, int col_off,
    float scale, int do_relu, int attn_mode)
{
    __shared__ float As[BK][BM + 2];   // +2 pad: conflict-free transposed stores
    __shared__ float Bs[BK][BN];

    const int tid = threadIdx.x;
    const int bm  = blockIdx.y * BM;
    const int bn  = blockIdx.x * BN;
    const int tx  = tid & 15;          // 0..15 (col groups)
    const int ty  = tid >> 4;          // 0..15 (row groups)

    // global load mapping
    const int a_row = tid >> 2;              // 0..63 (+64)
    const int a_col = (tid & 3) * 4;         // 0,4,8,12
    const int b_row = tid >> 5;              // 0..7 (+8)
    const int b_col = (tid & 31) * 4;        // 0..124

    float acc[8][8];
#pragma unroll
    for (int i = 0; i < 8; i++)
#pragma unroll
        for (int j = 0; j < 8; j++) acc[i][j] = 0.f;

    for (int k0 = 0; k0 < K; k0 += BK) {
        // load A tile (transposed into smem)
#pragma unroll
        for (int i = 0; i < 2; i++) {
            const int r = a_row + i * 64;
            const float4 v = *(const float4*)(A + (size_t)(bm + r) * K + k0 + a_col);
            As[a_col + 0][r] = v.x;
            As[a_col + 1][r] = v.y;
            As[a_col + 2][r] = v.z;
            As[a_col + 3][r] = v.w;
        }
        // load B tile
#pragma unroll
        for (int i = 0; i < 2; i++) {
            const int r = b_row + i * 8;
            float4 v = make_float4(0.f, 0.f, 0.f, 0.f);
            if (bn + b_col < N)
                v = *(const float4*)(B + (size_t)(k0 + r) * N + bn + b_col);
            *(float4*)(&Bs[r][b_col]) = v;
        }
        __syncthreads();

#pragma unroll
        for (int kk = 0; kk < BK; kk++) {
            float a_frag[8], b_frag[8];
#pragma unroll
            for (int i = 0; i < 4; i++) {
                a_frag[i]     = As[kk][ty * 4 + i];
                a_frag[i + 4] = As[kk][64 + ty * 4 + i];
            }
            const float4 bv0 = *(const float4*)(&Bs[kk][tx * 4]);
            const float4 bv1 = *(const float4*)(&Bs[kk][64 + tx * 4]);
            b_frag[0] = bv0.x; b_frag[1] = bv0.y; b_frag[2] = bv0.z; b_frag[3] = bv0.w;
            b_frag[4] = bv1.x; b_frag[5] = bv1.y; b_frag[6] = bv1.z; b_frag[7] = bv1.w;
#pragma unroll
            for (int i = 0; i < 8; i++)
#pragma unroll
                for (int j = 0; j < 8; j++)
                    acc[i][j] = fmaf(a_frag[i], b_frag[j], acc[i][j]);
        }
        __syncthreads();
    }

    // epilogue
#pragma unroll
    for (int i = 0; i < 8; i++) {
        const int r = bm + ((i < 4) ? (ty * 4 + i) : (64 + ty * 4 + (i - 4)));
#pragma unroll
        for (int j = 0; j < 8; j++) {
            const int c = bn + ((j < 4) ? (tx * 4 + j) : (64 + tx * 4 + (j - 4)));
            if (c < N) {
                float v = (acc[i][j] + bias[c]) * scale;
                if (do_relu) v = fmaxf(v, 0.f);
                if (attn_mode) {
                    const int b = r >> 10, nn = r & 1023;
                    const int h = c >> 6,  d  = c & 63;
                    C[(((size_t)(b * NHEAD + h) * SEQ) + nn) * HDIM + d] = v;
                } else {
                    C[(size_t)r * ldc + col_off + c] = v;
                }
            }
        }
    }
}

// ---------------------------------------------------------------------------
// Flash attention (fp32, diag-masked). One query per thread, 128 q / block,
// one (b,h) per blockIdx.y. K/V tiles of 32 rows in smem; broadcast float4
// reads. Writes attention output into g_CAT columns [0, 1024).
// ---------------------------------------------------------------------------
__global__ __launch_bounds__(128) void attn_kernel(
    const float* __restrict__ Q, const float* __restrict__ K,
    const float* __restrict__ V, float* __restrict__ OUT)
{
    __shared__ float Ks[32][64];
    __shared__ float Vs[32][64];

    const int tid = threadIdx.x;           // 0..127
    const int bh  = blockIdx.y;            // b*16 + h
    const int qi  = blockIdx.x * 128 + tid;

    const float* qptr = Q + ((size_t)bh * SEQ + qi) * HDIM;
    float q[64];
#pragma unroll
    for (int d = 0; d < 64; d += 4) {
        const float4 v = *(const float4*)(qptr + d);
        q[d] = v.x; q[d + 1] = v.y; q[d + 2] = v.z; q[d + 3] = v.w;
    }

    float o[64];
#pragma unroll
    for (int d = 0; d < 64; d++) o[d] = 0.f;
    float m = -1e30f, l = 0.f;

    const float* Kb = K + (size_t)bh * SEQ * HDIM;
    const float* Vb = V + (size_t)bh * SEQ * HDIM;

    for (int t = 0; t < SEQ; t += 32) {
        __syncthreads();
#pragma unroll
        for (int i = 0; i < 4; i++) {
            const int flat = tid + i * 128;        // float4 slot 0..511
            const int row = flat >> 4;
            const int c4  = (flat & 15) * 4;
            *(float4*)(&Ks[row][c4]) = *(const float4*)(Kb + (size_t)(t + row) * 64 + c4);
            *(float4*)(&Vs[row][c4]) = *(const float4*)(Vb + (size_t)(t + row) * 64 + c4);
        }
        __syncthreads();

        // scores s[j] = q . K[j]
        float s[32];
#pragma unroll
        for (int j = 0; j < 32; j++) {
            float a0 = 0.f, a1 = 0.f, a2 = 0.f, a3 = 0.f;
#pragma unroll
            for (int d = 0; d < 64; d += 4) {
                const float4 kv = *(const float4*)(&Ks[j][d]);
                a0 = fmaf(q[d],     kv.x, a0);
                a1 = fmaf(q[d + 1], kv.y, a1);
                a2 = fmaf(q[d + 2], kv.z, a2);
                a3 = fmaf(q[d + 3], kv.w, a3);
            }
            s[j] = (a0 + a1) + (a2 + a3);
        }

        // diagonal mask + running max
        float mt = m;
#pragma unroll
        for (int j = 0; j < 32; j++) {
            if (t + j == qi) s[j] = -1e30f;
            mt = fmaxf(mt, s[j]);
        }

        const float corr = __expf(m - mt);
        m = mt;
        l *= corr;
#pragma unroll
        for (int d = 0; d < 64; d++) o[d] *= corr;

#pragma unroll
        for (int j = 0; j < 32; j++) {
            const float p = __expf(s[j] - mt);
            l += p;
#pragma unroll
            for (int d = 0; d < 64; d += 4) {
                const float4 vv = *(const float4*)(&Vs[j][d]);
                o[d]     = fmaf(p, vv.x, o[d]);
                o[d + 1] = fmaf(p, vv.y, o[d + 1]);
                o[d + 2] = fmaf(p, vv.z, o[d + 2]);
                o[d + 3] = fmaf(p, vv.w, o[d + 3]);
            }
        }
    }

    const float inv = 1.f / l;
    const int b = bh >> 4, h = bh & 15;
    float* outp = OUT + ((size_t)(b * SEQ + qi)) * CATD + h * HDIM;
#pragma unroll
    for (int d = 0; d < 64; d += 4) {
        float4 v;
        v.x = o[d] * inv; v.y = o[d + 1] * inv;
        v.z = o[d + 2] * inv; v.w = o[d + 3] * inv;
        *(float4*)(outp + d) = v;
    }
}

// ---------------------------------------------------------------------------
// launch
// ---------------------------------------------------------------------------
extern "C" void kernel_launch(void* const* d_in, const int* in_sizes, int n_in,
                              void* d_out, int out_size)
{
    const float* x    = (const float*)d_in[0];
    const float* Wq   = (const float*)d_in[1];
    const float* bq   = (const float*)d_in[2];
    const float* Wk   = (const float*)d_in[3];
    const float* bk   = (const float*)d_in[4];
    const float* Wv   = (const float*)d_in[5];
    const float* bv   = (const float*)d_in[6];
    const float* Win  = (const float*)d_in[7];
    const float* bin_ = (const float*)d_in[8];
    const float* W1   = (const float*)d_in[9];
    const float* b1   = (const float*)d_in[10];
    const float* W2   = (const float*)d_in[11];
    const float* b2   = (const float*)d_in[12];
    float* out = (float*)d_out;

    float *qb, *kb, *vb, *cat, *h1;
    cudaGetSymbolAddress((void**)&qb,  g_Q);
    cudaGetSymbolAddress((void**)&kb,  g_K);
    cudaGetSymbolAddress((void**)&vb,  g_V);
    cudaGetSymbolAddress((void**)&cat, g_CAT);
    cudaGetSymbolAddress((void**)&h1,  g_H1);

    const float scaling = 0.125f;   // HEAD_DIM^-0.5

    dim3 blk(256);
    dim3 g_qkv(DIM / BN, MTOT / BM);       // (8, 64)
    // Q/K/V projections -> [b,h,n,d] scratch (Q pre-scaled)
    sgemm_kernel<<<g_qkv, blk>>>(x, Wq, bq, qb, MTOT, DIM, DIM, 0, 0, scaling, 0, 1);
    sgemm_kernel<<<g_qkv, blk>>>(x, Wk, bk, kb, MTOT, DIM, DIM, 0, 0, 1.0f, 0, 1);
    sgemm_kernel<<<g_qkv, blk>>>(x, Wv, bv, vb, MTOT, DIM, DIM, 0, 0, 1.0f, 0, 1);
    // in_ projection -> CAT columns [1024, 1088)
    dim3 g_in(1, MTOT / BM);               // (1, 64)
    sgemm_kernel<<<g_in, blk>>>(x, Win, bin_, cat, MTOT, HDIM, DIM, CATD, DIM, 1.0f, 0, 0);

    // flash attention -> CAT columns [0, 1024)
    dim3 g_att(SEQ / 128, BSZ * NHEAD);    // (8, 128)
    attn_kernel<<<g_att, dim3(128)>>>(qb, kb, vb, cat);

    // FFN
    dim3 g_f1(FFD / BN, MTOT / BM);        // (16, 64)
    sgemm_kernel<<<g_f1, blk>>>(cat, W1, b1, h1, MTOT, FFD, CATD, FFD, 0, 1.0f, 1, 0);
    dim3 g_f2(DIM / BN, MTOT / BM);        // (8, 64)
    sgemm_kernel<<<g_f2, blk>>>(h1, W2, b2, out, MTOT, DIM, FFD, DIM, 0, 1.0f, 0, 0);
}

// round 6
// speedup vs baseline: 2.0268x; 2.0268x over previous
#include <cuda_runtime.h>
#include <cstdint>
#include <cstddef>

// ---------------------------------------------------------------------------
// Problem constants
// ---------------------------------------------------------------------------
#define BSZ       8
#define SEQ       1024
#define DIM       1024
#define NHEAD     16
#define HDIM      64
#define MTOT      (BSZ * SEQ)        // 8192
#define CATD      (DIM + HDIM)       // 1088
#define FFD       (2 * DIM)          // 2048

// ---------------------------------------------------------------------------
// Scratch (static device globals; no allocation anywhere)
// ---------------------------------------------------------------------------
__device__ float g_Q[(size_t)BSZ * NHEAD * SEQ * HDIM];
__device__ float g_K[(size_t)BSZ * NHEAD * SEQ * HDIM];
__device__ float g_V[(size_t)BSZ * NHEAD * SEQ * HDIM];
__device__ float g_CAT[(size_t)MTOT * CATD];
__device__ float g_H1[(size_t)MTOT * FFD];

// Pre-permuted tf32 weights (fragment-major). Offsets in uint32 elements.
//  Wq/Wk/Wv: K=1024, Npad=1024 -> 1048576 each
//  Win:      K=1024, Npad=128  -> 131072
//  W1:       K=1088, Npad=2048 -> 2228224
//  W2:       K=2048, Npad=1024 -> 2097152
#define WP_Q   0
#define WP_K   1048576
#define WP_V   2097152
#define WP_IN  3145728
#define WP_1   3276800
#define WP_2   5505024
#define WP_TOT 7602176
__device__ uint32_t g_WP[WP_TOT];

// ---------------------------------------------------------------------------
// helpers
// ---------------------------------------------------------------------------
__device__ __forceinline__ uint32_t smem_u32(const void* p) {
    uint32_t a;
    asm("{ .reg .u64 t; cvta.to.shared.u64 t, %1; cvt.u32.u64 %0, t; }"
        : "=r"(a) : "l"(p));
    return a;
}
__device__ __forceinline__ uint32_t f32_tf32(float f) {
    uint32_t u;
    asm("cvt.rna.tf32.f32 %0, %1;" : "=r"(u) : "f"(f));
    return u;
}

// ---------------------------------------------------------------------------
// Weight permutation: W[k][n] (row-major, n-stride Nn) -> fragment-major tf32
//   dest[nblk][kblk][nt*4+kt][lane][reg]
//   frag (8k x 8n) for mma.m16n8k8 "col" B operand:
//     lane = (n&7)*4 + (k&3), reg = (k>>3 ? ... ) = (k&7)>>2
// Zero-fill for n >= Nn (Npad tiles).
// ---------------------------------------------------------------------------
__global__ void permute_w(const float* __restrict__ W, uint32_t* __restrict__ Wp,
                          int K, int Nn, int Npad)
{
    const int idx = blockIdx.x * 256 + threadIdx.x;
    const int rowlen4 = Npad >> 2;
    const int k = idx / rowlen4;
    if (k >= K) return;
    const int n4 = (idx - k * rowlen4) << 2;

    float4 v = make_float4(0.f, 0.f, 0.f, 0.f);
    if (n4 < Nn) v = *(const float4*)(W + (size_t)k * Nn + n4);

    const int nblk = n4 >> 7;
    const int nt   = (n4 >> 3) & 15;
    const int nnb  = n4 & 7;             // 0 or 4
    const int kblk = k >> 5;
    const int kt   = (k >> 3) & 3;
    const int kk   = k & 7;
    const int reg  = kk >> 2;
    const int kk3  = kk & 3;

    uint32_t* d = Wp + (size_t)nblk * K * 128 + (size_t)kblk * 4096
                     + (size_t)(nt * 4 + kt) * 64 + reg;
    d[((nnb + 0) * 4 + kk3) * 2] = f32_tf32(v.x);
    d[((nnb + 1) * 4 + kk3) * 2] = f32_tf32(v.y);
    d[((nnb + 2) * 4 + kk3) * 2] = f32_tf32(v.z);
    d[((nnb + 3) * 4 + kk3) * 2] = f32_tf32(v.w);
}

// ---------------------------------------------------------------------------
// tf32 mma.sync GEMM: C = op(A[M,K] @ W[K,N] + bias)
//   128x128 block tile, BK=32, 8 warps (64x32 warp tiles), m16n8k8 tf32.
//   A: gmem fp32 -> regs -> cvt.rna -> fragment-major smem (132-u32 frag stride)
//   B: pre-permuted tf32 gmem -> cp.async.cg 16KB contiguous per stage
// ---------------------------------------------------------------------------
#define BM 128
#define BN 128
#define A_FSTRIDE   132                       // uint32 per A frag (pad 128->132)
#define A_STAGE_U32 (32 * A_FSTRIDE)          // 4224
#define B_STAGE_U32 4096
#define STAGE_U32   (A_STAGE_U32 + B_STAGE_U32)   // 8320
#define GEMM_SMEM   (2 * STAGE_U32 * 4)       // 66560 bytes

__global__ __launch_bounds__(256, 2) void mma_gemm(
    const float* __restrict__ A, const uint32_t* __restrict__ Bp,
    const float* __restrict__ bias, float* __restrict__ C,
    int Nn, int K, int ldc, int col_off,
    float scale, int do_relu, int attn_mode)
{
    extern __shared__ uint32_t S[];
    const uint32_t sbase = smem_u32(S);
    const int tid  = threadIdx.x;
    const int lane = tid & 31;
    const int wid  = tid >> 5;
    const int g    = lane >> 2;
    const int tig  = lane & 3;
    const int wm   = wid >> 2;   // 0..1
    const int wn   = wid & 3;    // 0..3
    const int bm   = blockIdx.y * BM;
    const int bn   = blockIdx.x * BN;
    const int T    = K >> 5;

    // A load/store mapping (per thread: 4 float4s per stage)
    const int arow = tid >> 3;               // 0..31, +32 per i
    const int ac4  = (tid & 7) << 2;         // k offset within 32: 0..28
    const int a_kt   = ac4 >> 3;
    const int a_kkb  = ac4 & 7;              // 0 or 4
    const int a_regb = ((arow >> 3) & 1) /*rows 0..31: rr&15>=8 <=> (arow>>3)&1*/
                     + ((a_kkb >> 2) << 1);
    const int a_lb   = (arow & 7) << 2;      // (rr&7)*4

    const float*    Ag = A + (size_t)bm * K;
    const uint32_t* Bg = Bp + (size_t)blockIdx.x * K * 128;

    float acc[4][4][4];
#pragma unroll
    for (int i = 0; i < 4; i++)
#pragma unroll
        for (int j = 0; j < 4; j++)
#pragma unroll
            for (int r = 0; r < 4; r++) acc[i][j][r] = 0.f;

    float4 areg[4];

    auto LDG_A = [&](int t) {
#pragma unroll
        for (int i = 0; i < 4; i++) {
            const int row = arow + i * 32;
            areg[i] = *(const float4*)(Ag + (size_t)row * K + t * 32 + ac4);
        }
    };
    auto STS_A = [&](int s) {
        uint32_t* As = S + s * STAGE_U32;
#pragma unroll
        for (int i = 0; i < 4; i++) {
            const int mt = (arow + i * 32) >> 4;
            uint32_t* p = As + (mt * 4 + a_kt) * A_FSTRIDE + a_regb;
            p[(a_lb + 0) * 4] = f32_tf32(areg[i].x);
            p[(a_lb + 1) * 4] = f32_tf32(areg[i].y);
            p[(a_lb + 2) * 4] = f32_tf32(areg[i].z);
            p[(a_lb + 3) * 4] = f32_tf32(areg[i].w);
        }
    };
    auto CPA_B = [&](int t, int s) {
        const uint32_t dstb = sbase + (s * STAGE_U32 + A_STAGE_U32) * 4;
        const uint32_t* src = Bg + (size_t)t * 4096 + tid * 4;
#pragma unroll
        for (int i = 0; i < 4; i++) {
            asm volatile("cp.async.cg.shared.global [%0], [%1], 16;"
                         :: "r"(dstb + (uint32_t)(tid + i * 256) * 16),
                            "l"(src + i * 1024) : "memory");
        }
    };
    auto COMPUTE = [&](int s) {
        const uint32_t* As = S + s * STAGE_U32;
        const uint32_t* Bs = As + A_STAGE_U32;
#pragma unroll
        for (int kt = 0; kt < 4; kt++) {
            uint4 af[4];
            uint2 bf[4];
#pragma unroll
            for (int mi = 0; mi < 4; mi++)
                af[mi] = *(const uint4*)(As + ((wm * 4 + mi) * 4 + kt) * A_FSTRIDE
                                            + lane * 4);
#pragma unroll
            for (int ni = 0; ni < 4; ni++)
                bf[ni] = *(const uint2*)(Bs + ((wn * 4 + ni) * 4 + kt) * 64
                                            + lane * 2);
#pragma unroll
            for (int mi = 0; mi < 4; mi++)
#pragma unroll
                for (int ni = 0; ni < 4; ni++)
                    asm volatile(
                        "mma.sync.aligned.m16n8k8.row.col.f32.tf32.tf32.f32 "
                        "{%0,%1,%2,%3}, {%4,%5,%6,%7}, {%8,%9}, {%0,%1,%2,%3};"
                        : "+f"(acc[mi][ni][0]), "+f"(acc[mi][ni][1]),
                          "+f"(acc[mi][ni][2]), "+f"(acc[mi][ni][3])
                        : "r"(af[mi].x), "r"(af[mi].y), "r"(af[mi].z), "r"(af[mi].w),
                          "r"(bf[ni].x), "r"(bf[ni].y));
        }
    };

    // prologue
    CPA_B(0, 0);
    asm volatile("cp.async.commit_group;" ::: "memory");
    LDG_A(0);
    STS_A(0);

    for (int t = 0; t < T; t++) {
        const int s = t & 1;
        if (t + 1 < T) {
            CPA_B(t + 1, s ^ 1);
            asm volatile("cp.async.commit_group;" ::: "memory");
            LDG_A(t + 1);
            asm volatile("cp.async.wait_group 1;" ::: "memory");
        } else {
            asm volatile("cp.async.wait_group 0;" ::: "memory");
        }
        __syncthreads();
        COMPUTE(s);
        if (t + 1 < T) STS_A(s ^ 1);
        __syncthreads();
    }

    // epilogue: c0/c1 = row g cols 2tig..+1; c2/c3 = row g+8
#pragma unroll
    for (int mi = 0; mi < 4; mi++) {
        const int r0 = bm + (wm * 4 + mi) * 16 + g;
#pragma unroll
        for (int ni = 0; ni < 4; ni++) {
            const int c = bn + (wn * 4 + ni) * 8 + tig * 2;
            if (c < Nn) {
                const float2 bv = *(const float2*)(bias + c);
                float2 v0, v1;
                v0.x = (acc[mi][ni][0] + bv.x) * scale;
                v0.y = (acc[mi][ni][1] + bv.y) * scale;
                v1.x = (acc[mi][ni][2] + bv.x) * scale;
                v1.y = (acc[mi][ni][3] + bv.y) * scale;
                if (do_relu) {
                    v0.x = fmaxf(v0.x, 0.f); v0.y = fmaxf(v0.y, 0.f);
                    v1.x = fmaxf(v1.x, 0.f); v1.y = fmaxf(v1.y, 0.f);
                }
                if (attn_mode) {
                    const int h = c >> 6, d = c & 63;
                    const int b0 = r0 >> 10, nn0 = r0 & 1023;
                    *(float2*)(g_Q + 0) ; // (no-op placeholder removed below)
                    float* p0 = C + (((size_t)(b0 * NHEAD + h) * SEQ) + nn0) * HDIM + d;
                    *(float2*)p0 = v0;
                    const int r1 = r0 + 8;
                    const int b1 = r1 >> 10, nn1 = r1 & 1023;
                    float* p1 = C + (((size_t)(b1 * NHEAD + h) * SEQ) + nn1) * HDIM + d;
                    *(float2*)p1 = v1;
                } else {
                    *(float2*)(C + (size_t)r0 * ldc + col_off + c) = v0;
                    *(float2*)(C + (size_t)(r0 + 8) * ldc + col_off + c) = v1;
                }
            }
        }
    }
}

// ---------------------------------------------------------------------------
// Flash attention (fp32 SIMT, diag-masked) — unchanged from R3 (passing).
// ---------------------------------------------------------------------------
__global__ __launch_bounds__(128) void attn_kernel(
    const float* __restrict__ Q, const float* __restrict__ K,
    const float* __restrict__ V, float* __restrict__ OUT)
{
    __shared__ float Ks[32][64];
    __shared__ float Vs[32][64];

    const int tid = threadIdx.x;
    const int bh  = blockIdx.y;
    const int qi  = blockIdx.x * 128 + tid;

    const float* qptr = Q + ((size_t)bh * SEQ + qi) * HDIM;
    float q[64];
#pragma unroll
    for (int d = 0; d < 64; d += 4) {
        const float4 v = *(const float4*)(qptr + d);
        q[d] = v.x; q[d + 1] = v.y; q[d + 2] = v.z; q[d + 3] = v.w;
    }

    float o[64];
#pragma unroll
    for (int d = 0; d < 64; d++) o[d] = 0.f;
    float m = -1e30f, l = 0.f;

    const float* Kb = K + (size_t)bh * SEQ * HDIM;
    const float* Vb = V + (size_t)bh * SEQ * HDIM;

    for (int t = 0; t < SEQ; t += 32) {
        __syncthreads();
#pragma unroll
        for (int i = 0; i < 4; i++) {
            const int flat = tid + i * 128;
            const int row = flat >> 4;
            const int c4  = (flat & 15) * 4;
            *(float4*)(&Ks[row][c4]) = *(const float4*)(Kb + (size_t)(t + row) * 64 + c4);
            *(float4*)(&Vs[row][c4]) = *(const float4*)(Vb + (size_t)(t + row) * 64 + c4);
        }
        __syncthreads();

        float s[32];
#pragma unroll
        for (int j = 0; j < 32; j++) {
            float a0 = 0.f, a1 = 0.f, a2 = 0.f, a3 = 0.f;
#pragma unroll
            for (int d = 0; d < 64; d += 4) {
                const float4 kv = *(const float4*)(&Ks[j][d]);
                a0 = fmaf(q[d],     kv.x, a0);
                a1 = fmaf(q[d + 1], kv.y, a1);
                a2 = fmaf(q[d + 2], kv.z, a2);
                a3 = fmaf(q[d + 3], kv.w, a3);
            }
            s[j] = (a0 + a1) + (a2 + a3);
        }

        float mt = m;
#pragma unroll
        for (int j = 0; j < 32; j++) {
            if (t + j == qi) s[j] = -1e30f;
            mt = fmaxf(mt, s[j]);
        }

        const float corr = __expf(m - mt);
        m = mt;
        l *= corr;
#pragma unroll
        for (int d = 0; d < 64; d++) o[d] *= corr;

#pragma unroll
        for (int j = 0; j < 32; j++) {
            const float p = __expf(s[j] - mt);
            l += p;
#pragma unroll
            for (int d = 0; d < 64; d += 4) {
                const float4 vv = *(const float4*)(&Vs[j][d]);
                o[d]     = fmaf(p, vv.x, o[d]);
                o[d + 1] = fmaf(p, vv.y, o[d + 1]);
                o[d + 2] = fmaf(p, vv.z, o[d + 2]);
                o[d + 3] = fmaf(p, vv.w, o[d + 3]);
            }
        }
    }

    const float inv = 1.f / l;
    const int b = bh >> 4, h = bh & 15;
    float* outp = OUT + ((size_t)(b * SEQ + qi)) * CATD + h * HDIM;
#pragma unroll
    for (int d = 0; d < 64; d += 4) {
        float4 v;
        v.x = o[d] * inv; v.y = o[d + 1] * inv;
        v.z = o[d + 2] * inv; v.w = o[d + 3] * inv;
        *(float4*)(outp + d) = v;
    }
}

// ---------------------------------------------------------------------------
// launch
// ---------------------------------------------------------------------------
extern "C" void kernel_launch(void* const* d_in, const int* in_sizes, int n_in,
                              void* d_out, int out_size)
{
    const float* x    = (const float*)d_in[0];
    const float* Wq   = (const float*)d_in[1];
    const float* bq   = (const float*)d_in[2];
    const float* Wk   = (const float*)d_in[3];
    const float* bk   = (const float*)d_in[4];
    const float* Wv   = (const float*)d_in[5];
    const float* bv   = (const float*)d_in[6];
    const float* Win  = (const float*)d_in[7];
    const float* bin_ = (const float*)d_in[8];
    const float* W1   = (const float*)d_in[9];
    const float* b1   = (const float*)d_in[10];
    const float* W2   = (const float*)d_in[11];
    const float* b2   = (const float*)d_in[12];
    float* out = (float*)d_out;

    float *qb, *kb, *vb, *cat, *h1;
    uint32_t* wp;
    cudaGetSymbolAddress((void**)&qb,  g_Q);
    cudaGetSymbolAddress((void**)&kb,  g_K);
    cudaGetSymbolAddress((void**)&vb,  g_V);
    cudaGetSymbolAddress((void**)&cat, g_CAT);
    cudaGetSymbolAddress((void**)&h1,  g_H1);
    cudaGetSymbolAddress((void**)&wp,  g_WP);

    cudaFuncSetAttribute(mma_gemm, cudaFuncAttributeMaxDynamicSharedMemorySize,
                         GEMM_SMEM);

    // ---- weight permutation (fragment-major tf32) ----
    permute_w<<<(1024 * 1024 / 4) / 256, 256>>>(Wq,  wp + WP_Q,  1024, 1024, 1024);
    permute_w<<<(1024 * 1024 / 4) / 256, 256>>>(Wk,  wp + WP_K,  1024, 1024, 1024);
    permute_w<<<(1024 * 1024 / 4) / 256, 256>>>(Wv,  wp + WP_V,  1024, 1024, 1024);
    permute_w<<<(1024 * 128  / 4) / 256, 256>>>(Win, wp + WP_IN, 1024, 64,   128);
    permute_w<<<(1088 * 2048 / 4) / 256, 256>>>(W1,  wp + WP_1,  1088, 2048, 2048);
    permute_w<<<(2048 * 1024 / 4) / 256, 256>>>(W2,  wp + WP_2,  2048, 1024, 1024);

    const float scaling = 0.125f;   // HEAD_DIM^-0.5
    dim3 blk(256);

    // Q/K/V projections -> [b,h,n,d] scratch (Q pre-scaled)
    dim3 g_qkv(DIM / BN, MTOT / BM);          // (8, 64)
    mma_gemm<<<g_qkv, blk, GEMM_SMEM>>>(x, wp + WP_Q, bq, qb, DIM, DIM, 0, 0, scaling, 0, 1);
    mma_gemm<<<g_qkv, blk, GEMM_SMEM>>>(x, wp + WP_K, bk, kb, DIM, DIM, 0, 0, 1.0f, 0, 1);
    mma_gemm<<<g_qkv, blk, GEMM_SMEM>>>(x, wp + WP_V, bv, vb, DIM, DIM, 0, 0, 1.0f, 0, 1);

    // in_ projection -> CAT columns [1024, 1088)
    dim3 g_in(1, MTOT / BM);                  // (1, 64)
    mma_gemm<<<g_in, blk, GEMM_SMEM>>>(x, wp + WP_IN, bin_, cat, HDIM, DIM, CATD, DIM, 1.0f, 0, 0);

    // flash attention -> CAT columns [0, 1024)
    dim3 g_att(SEQ / 128, BSZ * NHEAD);       // (8, 128)
    attn_kernel<<<g_att, dim3(128)>>>(qb, kb, vb, cat);

    // FFN
    dim3 g_f1(FFD / BN, MTOT / BM);           // (16, 64)
    mma_gemm<<<g_f1, blk, GEMM_SMEM>>>(cat, wp + WP_1, b1, h1, FFD, CATD, FFD, 0, 1.0f, 1, 0);
    dim3 g_f2(DIM / BN, MTOT / BM);           // (8, 64)
    mma_gemm<<<g_f2, blk, GEMM_SMEM>>>(h1, wp + WP_2, b2, out, DIM, FFD, DIM, 0, 1.0f, 0, 0);
}

// round 8
// speedup vs baseline: 4.0634x; 2.0049x over previous
#include <cuda_runtime.h>
#include <cstdint>
#include <cstddef>

// ---------------------------------------------------------------------------
// Problem constants
// ---------------------------------------------------------------------------
#define BSZ       8
#define SEQ       1024
#define DIM       1024
#define NHEAD     16
#define HDIM      64
#define MTOT      (BSZ * SEQ)        // 8192
#define CATD      (DIM + HDIM)       // 1088
#define FFD       (2 * DIM)          // 2048
#define L2E       1.4426950408889634f

// ---------------------------------------------------------------------------
// Scratch (static device globals; no allocation anywhere)
// ---------------------------------------------------------------------------
__device__ float g_CAT[(size_t)MTOT * CATD];
__device__ float g_H1[(size_t)MTOT * FFD];

// Fragment-major tf32 Q/K/V per (b,h): 65536 u32 each, 128 bh slots.
//  Q: [qt 64][ks 8][lane 32][reg 4]   (m16n8k8 A-fragments, rows=query, k=d)
//  K: [nt 128][ks 8][lane 32][reg 2]  (B-frags for S=Q.K^T, keys column-permuted)
//  V: [kk 128][dt 8][lane 32][reg 2]  (B-frags for O=P.V, natural key order)
__device__ uint32_t g_QF[(size_t)128 * 65536];
__device__ uint32_t g_KF[(size_t)128 * 65536];
__device__ uint32_t g_VF[(size_t)128 * 65536];

// Pre-permuted tf32 weights (fragment-major B operands). u32 offsets.
#define WP_Q   0
#define WP_K   1048576
#define WP_V   2097152
#define WP_IN  3145728
#define WP_1   3276800
#define WP_2   5505024
#define WP_TOT 7602176
__device__ uint32_t g_WP[WP_TOT];

// ---------------------------------------------------------------------------
// helpers
// ---------------------------------------------------------------------------
__device__ __forceinline__ uint32_t smem_u32(const void* p) {
    uint32_t a;
    asm("{ .reg .u64 t; cvta.to.shared.u64 t, %1; cvt.u32.u64 %0, t; }"
        : "=r"(a) : "l"(p));
    return a;
}
__device__ __forceinline__ uint32_t f32_tf32(float f) {
    uint32_t u;
    asm("cvt.rna.tf32.f32 %0, %1;" : "=r"(u) : "f"(f));
    return u;
}
__device__ __forceinline__ void mma_tf32(float* c, uint4 a, uint32_t b0, uint32_t b1) {
    asm volatile(
        "mma.sync.aligned.m16n8k8.row.col.f32.tf32.tf32.f32 "
        "{%0,%1,%2,%3}, {%4,%5,%6,%7}, {%8,%9}, {%0,%1,%2,%3};"
        : "+f"(c[0]), "+f"(c[1]), "+f"(c[2]), "+f"(c[3])
        : "r"(a.x), "r"(a.y), "r"(a.z), "r"(a.w), "r"(b0), "r"(b1));
}

// ---------------------------------------------------------------------------
// Weight permutation: W[k][n] -> fragment-major tf32 B operand
// ---------------------------------------------------------------------------
__global__ void permute_w(const float* __restrict__ W, uint32_t* __restrict__ Wp,
                          int K, int Nn, int Npad)
{
    const int idx = blockIdx.x * 256 + threadIdx.x;
    const int rowlen4 = Npad >> 2;
    const int k = idx / rowlen4;
    if (k >= K) return;
    const int n4 = (idx - k * rowlen4) << 2;

    float4 v = make_float4(0.f, 0.f, 0.f, 0.f);
    if (n4 < Nn) v = *(const float4*)(W + (size_t)k * Nn + n4);

    const int nblk = n4 >> 7;
    const int nt   = (n4 >> 3) & 15;
    const int nnb  = n4 & 7;
    const int kblk = k >> 5;
    const int kt   = (k >> 3) & 3;
    const int kk   = k & 7;
    const int reg  = kk >> 2;
    const int kk3  = kk & 3;

    uint32_t* d = Wp + (size_t)nblk * K * 128 + (size_t)kblk * 4096
                     + (size_t)(nt * 4 + kt) * 64 + reg;
    d[((nnb + 0) * 4 + kk3) * 2] = f32_tf32(v.x);
    d[((nnb + 1) * 4 + kk3) * 2] = f32_tf32(v.y);
    d[((nnb + 2) * 4 + kk3) * 2] = f32_tf32(v.z);
    d[((nnb + 3) * 4 + kk3) * 2] = f32_tf32(v.w);
}

// ---------------------------------------------------------------------------
// tf32 mma.sync GEMM: C = op(A[M,K] @ W[K,N] + bias)
//   mode 0: standard float store  mode 1/2/3: Q/K/V fragment scatter (tf32)
// ---------------------------------------------------------------------------
#define BM 128
#define BN 128
#define A_FSTRIDE   132
#define A_STAGE_U32 (32 * A_FSTRIDE)
#define B_STAGE_U32 4096
#define STAGE_U32   (A_STAGE_U32 + B_STAGE_U32)
#define GEMM_SMEM   (2 * STAGE_U32 * 4)

__global__ __launch_bounds__(256, 2) void mma_gemm(
    const float* __restrict__ A, const uint32_t* __restrict__ Bp,
    const float* __restrict__ bias, void* __restrict__ Cv,
    int Nn, int K, int ldc, int col_off,
    float scale, int do_relu, int mode)
{
    extern __shared__ uint32_t S[];
    const uint32_t sbase = smem_u32(S);
    const int tid  = threadIdx.x;
    const int lane = tid & 31;
    const int wid  = tid >> 5;
    const int g    = lane >> 2;
    const int tig  = lane & 3;
    const int wm   = wid >> 2;
    const int wn   = wid & 3;
    const int bm   = blockIdx.y * BM;
    const int bn   = blockIdx.x * BN;
    const int T    = K >> 5;

    const int arow = tid >> 3;
    const int ac4  = (tid & 7) << 2;
    const int a_kt   = ac4 >> 3;
    const int a_kkb  = ac4 & 7;
    const int a_regb = ((arow >> 3) & 1) + ((a_kkb >> 2) << 1);
    const int a_lb   = (arow & 7) << 2;

    const float*    Ag = A + (size_t)bm * K;
    const uint32_t* Bg = Bp + (size_t)blockIdx.x * K * 128;

    float acc[4][4][4];
#pragma unroll
    for (int i = 0; i < 4; i++)
#pragma unroll
        for (int j = 0; j < 4; j++)
#pragma unroll
            for (int r = 0; r < 4; r++) acc[i][j][r] = 0.f;

    float4 areg[4];

    auto LDG_A = [&](int t) {
#pragma unroll
        for (int i = 0; i < 4; i++) {
            const int row = arow + i * 32;
            areg[i] = *(const float4*)(Ag + (size_t)row * K + t * 32 + ac4);
        }
    };
    auto STS_A = [&](int s) {
        uint32_t* As = S + s * STAGE_U32;
#pragma unroll
        for (int i = 0; i < 4; i++) {
            const int mt = (arow + i * 32) >> 4;
            uint32_t* p = As + (mt * 4 + a_kt) * A_FSTRIDE + a_regb;
            p[(a_lb + 0) * 4] = f32_tf32(areg[i].x);
            p[(a_lb + 1) * 4] = f32_tf32(areg[i].y);
            p[(a_lb + 2) * 4] = f32_tf32(areg[i].z);
            p[(a_lb + 3) * 4] = f32_tf32(areg[i].w);
        }
    };
    auto CPA_B = [&](int t, int s) {
        const uint32_t dstb = sbase + (s * STAGE_U32 + A_STAGE_U32) * 4;
        const uint32_t* src = Bg + (size_t)t * 4096 + tid * 4;
#pragma unroll
        for (int i = 0; i < 4; i++) {
            asm volatile("cp.async.cg.shared.global [%0], [%1], 16;"
                         :: "r"(dstb + (uint32_t)(tid + i * 256) * 16),
                            "l"(src + i * 1024) : "memory");
        }
    };
    auto COMPUTE = [&](int s) {
        const uint32_t* As = S + s * STAGE_U32;
        const uint32_t* Bs = As + A_STAGE_U32;
#pragma unroll
        for (int kt = 0; kt < 4; kt++) {
            uint4 af[4];
            uint2 bf[4];
#pragma unroll
            for (int mi = 0; mi < 4; mi++)
                af[mi] = *(const uint4*)(As + ((wm * 4 + mi) * 4 + kt) * A_FSTRIDE
                                            + lane * 4);
#pragma unroll
            for (int ni = 0; ni < 4; ni++)
                bf[ni] = *(const uint2*)(Bs + ((wn * 4 + ni) * 4 + kt) * 64
                                            + lane * 2);
#pragma unroll
            for (int mi = 0; mi < 4; mi++)
#pragma unroll
                for (int ni = 0; ni < 4; ni++)
                    mma_tf32(acc[mi][ni], af[mi], bf[ni].x, bf[ni].y);
        }
    };

    CPA_B(0, 0);
    asm volatile("cp.async.commit_group;" ::: "memory");
    LDG_A(0);
    STS_A(0);

    for (int t = 0; t < T; t++) {
        const int s = t & 1;
        if (t + 1 < T) {
            CPA_B(t + 1, s ^ 1);
            asm volatile("cp.async.commit_group;" ::: "memory");
            LDG_A(t + 1);
            asm volatile("cp.async.wait_group 1;" ::: "memory");
        } else {
            asm volatile("cp.async.wait_group 0;" ::: "memory");
        }
        __syncthreads();
        COMPUTE(s);
        if (t + 1 < T) STS_A(s ^ 1);
        __syncthreads();
    }

    if (mode == 0) {
        float* C = (float*)Cv;
#pragma unroll
        for (int mi = 0; mi < 4; mi++) {
            const int r0 = bm + (wm * 4 + mi) * 16 + g;
#pragma unroll
            for (int ni = 0; ni < 4; ni++) {
                const int c = bn + (wn * 4 + ni) * 8 + tig * 2;
                if (c < Nn) {
                    const float2 bv = *(const float2*)(bias + c);
                    float2 v0, v1;
                    v0.x = (acc[mi][ni][0] + bv.x) * scale;
                    v0.y = (acc[mi][ni][1] + bv.y) * scale;
                    v1.x = (acc[mi][ni][2] + bv.x) * scale;
                    v1.y = (acc[mi][ni][3] + bv.y) * scale;
                    if (do_relu) {
                        v0.x = fmaxf(v0.x, 0.f); v0.y = fmaxf(v0.y, 0.f);
                        v1.x = fmaxf(v1.x, 0.f); v1.y = fmaxf(v1.y, 0.f);
                    }
                    *(float2*)(C + (size_t)r0 * ldc + col_off + c) = v0;
                    *(float2*)(C + (size_t)(r0 + 8) * ldc + col_off + c) = v1;
                }
            }
        }
    } else {
        uint32_t* Cu = (uint32_t*)Cv;
        auto store_frag = [&](int r, int cc, float v) {
            const int b = r >> 10, seq = r & 1023;
            const int h = cc >> 6, d = cc & 63;
            const uint32_t base = (uint32_t)(b * 16 + h) * 65536u;
            uint32_t addr;
            if (mode == 1) {          // Q: A-frag
                addr = base + (uint32_t)((seq >> 4) * 8 + (d >> 3)) * 128u
                     + (uint32_t)((seq & 7) * 4 + (d & 3)) * 4u
                     + (uint32_t)(((seq >> 3) & 1) + 2 * ((d >> 2) & 1));
            } else if (mode == 2) {   // K: B-frag, permuted key columns
                const uint32_t j = (uint32_t)(((seq & 3) << 1) | ((seq >> 2) & 1));
                addr = base + (uint32_t)((seq >> 3) * 8 + (d >> 3)) * 64u
                     + (j * 4 + (uint32_t)(d & 3)) * 2u + (uint32_t)((d >> 2) & 1);
            } else {                  // V: B-frag, natural order
                addr = base + (uint32_t)((seq >> 3) * 8 + (d >> 3)) * 64u
                     + (uint32_t)((d & 7) * 4 + (seq & 3)) * 2u
                     + (uint32_t)((seq >> 2) & 1);
            }
            Cu[addr] = f32_tf32(v);
        };
#pragma unroll
        for (int mi = 0; mi < 4; mi++) {
            const int r0 = bm + (wm * 4 + mi) * 16 + g;
#pragma unroll
            for (int ni = 0; ni < 4; ni++) {
                const int c = bn + (wn * 4 + ni) * 8 + tig * 2;
                const float2 bv = *(const float2*)(bias + c);
                store_frag(r0,     c,     (acc[mi][ni][0] + bv.x) * scale);
                store_frag(r0,     c + 1, (acc[mi][ni][1] + bv.y) * scale);
                store_frag(r0 + 8, c,     (acc[mi][ni][2] + bv.x) * scale);
                store_frag(r0 + 8, c + 1, (acc[mi][ni][3] + bv.y) * scale);
            }
        }
    }
}

// ---------------------------------------------------------------------------
// Flash attention via tf32 mma.sync.
//   grid (8 q-blocks, 128 bh), 256 threads = 8 warps, 16 queries/warp.
//   KV tiles of 128 keys, double-buffered cp.async (smem 128KB).
//   S output frags reinterpret directly as P A-frags (key-permuted K layout).
// ---------------------------------------------------------------------------
#define ATT_SMEM (2 * 16384 * 4)      // 131072 B

__global__ __launch_bounds__(256, 1) void attn_mma(
    const uint32_t* __restrict__ Qf, const uint32_t* __restrict__ Kf,
    const uint32_t* __restrict__ Vf, float* __restrict__ OUT)
{
    extern __shared__ uint32_t S[];   // [2][K 8192 | V 8192]
    const uint32_t sbase = smem_u32(S);
    const int tid  = threadIdx.x;
    const int lane = tid & 31;
    const int w    = tid >> 5;
    const int g    = lane >> 2;
    const int tig  = lane & 3;
    const int qb   = blockIdx.x;
    const int bh   = blockIdx.y;

    const uint32_t* Qb = Qf + (size_t)bh * 65536;
    const uint32_t* Kb = Kf + (size_t)bh * 65536;
    const uint32_t* Vb = Vf + (size_t)bh * 65536;

    // Q fragments for this warp's 16 query rows (coalesced LDG.128)
    uint4 qf[8];
    {
        const uint32_t* qp = Qb + (size_t)((qb * 8 + w) * 8) * 128 + lane * 4;
#pragma unroll
        for (int ks = 0; ks < 8; ks++)
            qf[ks] = *(const uint4*)(qp + ks * 128);
    }

    float o[8][4];
#pragma unroll
    for (int dt = 0; dt < 8; dt++)
#pragma unroll
        for (int r = 0; r < 4; r++) o[dt][r] = 0.f;
    float m0 = -1e30f, m1 = -1e30f, l0 = 0.f, l1 = 0.f;

    auto CPA = [&](int t, int s) {
        const uint32_t kd = sbase + (uint32_t)(s * 16384) * 4 + tid * 16;
        const uint32_t vd = kd + 8192 * 4;
        const uint32_t* ks_ = Kb + (size_t)t * 8192 + tid * 4;
        const uint32_t* vs_ = Vb + (size_t)t * 8192 + tid * 4;
#pragma unroll
        for (int i = 0; i < 8; i++) {
            asm volatile("cp.async.cg.shared.global [%0], [%1], 16;"
                         :: "r"(kd + i * 4096u), "l"(ks_ + i * 1024) : "memory");
            asm volatile("cp.async.cg.shared.global [%0], [%1], 16;"
                         :: "r"(vd + i * 4096u), "l"(vs_ + i * 1024) : "memory");
        }
    };

    CPA(0, 0);
    asm volatile("cp.async.commit_group;" ::: "memory");

    for (int t = 0; t < 8; t++) {
        const int s = t & 1;
        asm volatile("cp.async.wait_group 0;" ::: "memory");
        __syncthreads();
        if (t + 1 < 8) {
            CPA(t + 1, s ^ 1);
            asm volatile("cp.async.commit_group;" ::: "memory");
        }
        const uint32_t* Ksm = S + s * 16384;
        const uint32_t* Vsm = Ksm + 8192;

        // S = Q . K^T  (16 n-tiles of 8 keys)
        float sc[16][4];
#pragma unroll
        for (int nt = 0; nt < 16; nt++) {
            sc[nt][0] = 0.f; sc[nt][1] = 0.f; sc[nt][2] = 0.f; sc[nt][3] = 0.f;
#pragma unroll
            for (int ks = 0; ks < 8; ks++) {
                const uint2 b = *(const uint2*)(Ksm + (nt * 8 + ks) * 64 + lane * 2);
                mma_tf32(sc[nt], qf[ks], b.x, b.y);
            }
        }

        // diag mask (only when key block == query block)
        // frag layout (post key-permute): sc0:(g,tig) sc1:(g,tig+4) sc2:(g+8,tig) sc3:(g+8,tig+4)
        if (t == qb) {
            const int q0 = w * 16 + g;
#pragma unroll
            for (int nt = 0; nt < 16; nt++) {
                const int k0 = nt * 8 + tig;
                if (k0     == q0)     sc[nt][0] = -1e30f;
                if (k0 + 4 == q0)     sc[nt][1] = -1e30f;
                if (k0     == q0 + 8) sc[nt][2] = -1e30f;
                if (k0 + 4 == q0 + 8) sc[nt][3] = -1e30f;
            }
        }

        // online softmax
        float mt0 = -1e30f, mt1 = -1e30f;
#pragma unroll
        for (int nt = 0; nt < 16; nt++) {
            mt0 = fmaxf(mt0, fmaxf(sc[nt][0], sc[nt][1]));
            mt1 = fmaxf(mt1, fmaxf(sc[nt][2], sc[nt][3]));
        }
        mt0 = fmaxf(mt0, __shfl_xor_sync(0xFFFFFFFFu, mt0, 1));
        mt0 = fmaxf(mt0, __shfl_xor_sync(0xFFFFFFFFu, mt0, 2));
        mt1 = fmaxf(mt1, __shfl_xor_sync(0xFFFFFFFFu, mt1, 1));
        mt1 = fmaxf(mt1, __shfl_xor_sync(0xFFFFFFFFu, mt1, 2));
        const float nm0 = fmaxf(m0, mt0), nm1 = fmaxf(m1, mt1);
        const float cr0 = exp2f((m0 - nm0) * L2E);
        const float cr1 = exp2f((m1 - nm1) * L2E);
        m0 = nm0; m1 = nm1;
        l0 *= cr0; l1 *= cr1;
#pragma unroll
        for (int dt = 0; dt < 8; dt++) {
            o[dt][0] *= cr0; o[dt][1] *= cr0;
            o[dt][2] *= cr1; o[dt][3] *= cr1;
        }
        const float b0 = nm0 * L2E, b1 = nm1 * L2E;
#pragma unroll
        for (int nt = 0; nt < 16; nt++) {
            const float p0 = exp2f(fmaf(sc[nt][0], L2E, -b0));
            const float p1 = exp2f(fmaf(sc[nt][1], L2E, -b0));
            const float p2 = exp2f(fmaf(sc[nt][2], L2E, -b1));
            const float p3 = exp2f(fmaf(sc[nt][3], L2E, -b1));
            l0 += p0 + p1; l1 += p2 + p3;
            // repack as PV A-frag: a0=(g,tig)=p0 a1=(g+8,tig)=p2 a2=(g,tig+4)=p1 a3=p3
            sc[nt][0] = __uint_as_float(f32_tf32(p0));
            sc[nt][1] = __uint_as_float(f32_tf32(p2));
            sc[nt][2] = __uint_as_float(f32_tf32(p1));
            sc[nt][3] = __uint_as_float(f32_tf32(p3));
        }

        // O += P . V
#pragma unroll
        for (int kk = 0; kk < 16; kk++) {
            const uint4 a = make_uint4(__float_as_uint(sc[kk][0]),
                                       __float_as_uint(sc[kk][1]),
                                       __float_as_uint(sc[kk][2]),
                                       __float_as_uint(sc[kk][3]));
#pragma unroll
            for (int dt = 0; dt < 8; dt++) {
                const uint2 b = *(const uint2*)(Vsm + (kk * 8 + dt) * 64 + lane * 2);
                mma_tf32(o[dt], a, b.x, b.y);
            }
        }
    }

    // finalize
    l0 += __shfl_xor_sync(0xFFFFFFFFu, l0, 1);
    l0 += __shfl_xor_sync(0xFFFFFFFFu, l0, 2);
    l1 += __shfl_xor_sync(0xFFFFFFFFu, l1, 1);
    l1 += __shfl_xor_sync(0xFFFFFFFFu, l1, 2);
    const float inv0 = 1.f / l0, inv1 = 1.f / l1;

    const int b_ = bh >> 4, h = bh & 15;
    const int q0 = qb * 128 + w * 16 + g;
    float* base0 = OUT + ((size_t)(b_ * 1024 + q0)) * CATD + h * 64 + tig * 2;
    float* base1 = base0 + (size_t)8 * CATD;
#pragma unroll
    for (int dt = 0; dt < 8; dt++) {
        float2 v0, v1;
        v0.x = o[dt][0] * inv0; v0.y = o[dt][1] * inv0;
        v1.x = o[dt][2] * inv1; v1.y = o[dt][3] * inv1;
        *(float2*)(base0 + dt * 8) = v0;
        *(float2*)(base1 + dt * 8) = v1;
    }
}

// ---------------------------------------------------------------------------
// launch
// ---------------------------------------------------------------------------
extern "C" void kernel_launch(void* const* d_in, const int* in_sizes, int n_in,
                              void* d_out, int out_size)
{
    const float* x    = (const float*)d_in[0];
    const float* Wq   = (const float*)d_in[1];
    const float* bq   = (const float*)d_in[2];
    const float* Wk   = (const float*)d_in[3];
    const float* bk   = (const float*)d_in[4];
    const float* Wv   = (const float*)d_in[5];
    const float* bv   = (const float*)d_in[6];
    const float* Win  = (const float*)d_in[7];
    const float* bin_ = (const float*)d_in[8];
    const float* W1   = (const float*)d_in[9];
    const float* b1   = (const float*)d_in[10];
    const float* W2   = (const float*)d_in[11];
    const float* b2   = (const float*)d_in[12];
    float* out = (float*)d_out;

    float *cat, *h1;
    uint32_t *wp, *qf, *kf, *vf;
    cudaGetSymbolAddress((void**)&cat, g_CAT);
    cudaGetSymbolAddress((void**)&h1,  g_H1);
    cudaGetSymbolAddress((void**)&wp,  g_WP);
    cudaGetSymbolAddress((void**)&qf,  g_QF);
    cudaGetSymbolAddress((void**)&kf,  g_KF);
    cudaGetSymbolAddress((void**)&vf,  g_VF);

    cudaFuncSetAttribute(mma_gemm, cudaFuncAttributeMaxDynamicSharedMemorySize,
                         GEMM_SMEM);
    cudaFuncSetAttribute(attn_mma, cudaFuncAttributeMaxDynamicSharedMemorySize,
                         ATT_SMEM);

    // ---- weight permutation (fragment-major tf32) ----
    permute_w<<<(1024 * 1024 / 4) / 256, 256>>>(Wq,  wp + WP_Q,  1024, 1024, 1024);
    permute_w<<<(1024 * 1024 / 4) / 256, 256>>>(Wk,  wp + WP_K,  1024, 1024, 1024);
    permute_w<<<(1024 * 1024 / 4) / 256, 256>>>(Wv,  wp + WP_V,  1024, 1024, 1024);
    permute_w<<<(1024 * 128  / 4) / 256, 256>>>(Win, wp + WP_IN, 1024, 64,   128);
    permute_w<<<(1088 * 2048 / 4) / 256, 256>>>(W1,  wp + WP_1,  1088, 2048, 2048);
    permute_w<<<(2048 * 1024 / 4) / 256, 256>>>(W2,  wp + WP_2,  2048, 1024, 1024);

    const float scaling = 0.125f;   // HEAD_DIM^-0.5
    dim3 blk(256);

    // Q/K/V projections -> fragment-major tf32 scratch (Q pre-scaled)
    dim3 g_qkv(DIM / BN, MTOT / BM);          // (8, 64)
    mma_gemm<<<g_qkv, blk, GEMM_SMEM>>>(x, wp + WP_Q, bq, qf, DIM, DIM, 0, 0, scaling, 0, 1);
    mma_gemm<<<g_qkv, blk, GEMM_SMEM>>>(x, wp + WP_K, bk, kf, DIM, DIM, 0, 0, 1.0f, 0, 2);
    mma_gemm<<<g_qkv, blk, GEMM_SMEM>>>(x, wp + WP_V, bv, vf, DIM, DIM, 0, 0, 1.0f, 0, 3);

    // in_ projection -> CAT columns [1024, 1088)
    dim3 g_in(1, MTOT / BM);                  // (1, 64)
    mma_gemm<<<g_in, blk, GEMM_SMEM>>>(x, wp + WP_IN, bin_, cat, HDIM, DIM, CATD, DIM, 1.0f, 0, 0);

    // flash attention (tensor cores) -> CAT columns [0, 1024)
    dim3 g_att(8, BSZ * NHEAD);               // (8, 128)
    attn_mma<<<g_att, blk, ATT_SMEM>>>(qf, kf, vf, cat);

    // FFN
    dim3 g_f1(FFD / BN, MTOT / BM);           // (16, 64)
    mma_gemm<<<g_f1, blk, GEMM_SMEM>>>(cat, wp + WP_1, b1, h1, FFD, CATD, FFD, 0, 1.0f, 1, 0);
    dim3 g_f2(DIM / BN, MTOT / BM);           // (8, 64)
    mma_gemm<<<g_f2, blk, GEMM_SMEM>>>(h1, wp + WP_2, b2, out, DIM, FFD, DIM, 0, 1.0f, 0, 0);
}